// round 10
// baseline (speedup 1.0000x reference)
#include <cuda_runtime.h>
#include <cstdint>
#include <cstddef>

#define B_ 128
#define N_ 196
#define E_ 2048
#define D_ 512
#define A_ 512
#define M_ (B_*N_)   // 25088

// ---- device scratch (allocation-free rule) ----
__device__ float g_c2[B_*A_];         // att2 + bd + be, [B][A]
__device__ float g_sp[M_*8];          // partial scores, 8 slices per row
__device__ uint32_t g_Wp[A_*(E_/2)]; // We packed: [n][k/2] fp16x2 (low=even k)
__device__ float g_dummy[32];

// ---- helpers ----
__device__ __forceinline__ uint32_t pack2(float lo, float hi){
    uint32_t r; asm("cvt.rn.f16x2.f32 %0, %1, %2;" : "=r"(r) : "f"(hi), "f"(lo));
    return r;
}
__device__ __forceinline__ void mma16(float&d0,float&d1,float&d2,float&d3,
    uint32_t a0,uint32_t a1,uint32_t a2,uint32_t a3,uint32_t b0,uint32_t b1){
    asm volatile("mma.sync.aligned.m16n8k16.row.col.f32.f16.f16.f32 "
        "{%0,%1,%2,%3},{%4,%5,%6,%7},{%8,%9},{%0,%1,%2,%3};\n"
        : "+f"(d0),"+f"(d1),"+f"(d2),"+f"(d3)
        : "r"(a0),"r"(a1),"r"(a2),"r"(a3),"r"(b0),"r"(b1));
}
__device__ __forceinline__ uint32_t smem_u32(const void* p){
    uint32_t a;
    asm("{ .reg .u64 t; cvta.to.shared.u64 t, %1; cvt.u32.u64 %0, t; }" : "=r"(a) : "l"(p));
    return a;
}
__device__ __forceinline__ void cpasync16(uint32_t dst, const void* src){
    asm volatile("cp.async.cg.shared.global [%0], [%1], 16;" :: "r"(dst), "l"(src));
}
#define CP_COMMIT() asm volatile("cp.async.commit_group;" ::: "memory")
#define CP_WAIT1()  asm volatile("cp.async.wait_group 1;" ::: "memory")
#define CP_WAIT0()  asm volatile("cp.async.wait_group 0;" ::: "memory")

// ============================================================
// K0: pack We [E][A] fp32 -> g_Wp [A][E/2] fp16x2 (k-pairs)
// ============================================================
__global__ __launch_bounds__(256) void pack_we(const float* __restrict__ We)
{
    __shared__ float s[64][33];
    const int k0 = blockIdx.x * 64, n0 = blockIdx.y * 32;
    const int tx = threadIdx.x, ty = threadIdx.y;
    #pragma unroll
    for (int j = ty; j < 64; j += 8)
        s[j][tx] = We[(size_t)(k0 + j)*A_ + n0 + tx];
    __syncthreads();
    const int kp0 = blockIdx.x * 32;
    #pragma unroll
    for (int j = ty; j < 32; j += 8)
        g_Wp[(size_t)(n0 + j)*(E_/2) + kp0 + tx] = pack2(s[2*tx][j], s[2*tx+1][j]);
}

// ============================================================
// K1: g_c2[b][a] = dec[b]@Wd[:,a] + bd[a] + be[a]
// ============================================================
__global__ __launch_bounds__(256) void att2_kernel(
    const float* __restrict__ dec, const float* __restrict__ Wd,
    const float* __restrict__ bd,  const float* __restrict__ be)
{
    __shared__ float sDec[16*D_];
    const int tid = threadIdx.x;
    const int a0 = blockIdx.x*128, b0 = blockIdx.y*16;

    const float4* src = (const float4*)(dec + (size_t)b0*D_);
    float4* dst = (float4*)sDec;
    for (int i=tid; i<16*D_/4; i+=256) dst[i] = src[i];
    __syncthreads();

    const int tx = tid & 31, ty = tid >> 5;
    const float4* wp = (const float4*)(Wd + a0) + tx;
    float4 acc0 = {0,0,0,0}, acc1 = {0,0,0,0};
    for (int d=0; d<D_; d++){
        float4 w = wp[(size_t)d*(A_/4)];
        float x0 = sDec[ty*D_ + d];
        float x1 = sDec[(ty+8)*D_ + d];
        acc0.x += w.x*x0; acc0.y += w.y*x0; acc0.z += w.z*x0; acc0.w += w.w*x0;
        acc1.x += w.x*x1; acc1.y += w.y*x1; acc1.z += w.z*x1; acc1.w += w.w*x1;
    }
    const int a = a0 + tx*4;
    float bx = bd[a]   + be[a];
    float by = bd[a+1] + be[a+1];
    float bz = bd[a+2] + be[a+2];
    float bw = bd[a+3] + be[a+3];
    float4 o0 = {acc0.x+bx, acc0.y+by, acc0.z+bz, acc0.w+bw};
    float4 o1 = {acc1.x+bx, acc1.y+by, acc1.z+bz, acc1.w+bw};
    *(float4*)&g_c2[(size_t)(b0+ty  )*A_ + a] = o0;
    *(float4*)&g_c2[(size_t)(b0+ty+8)*A_ + a] = o1;
}

// dummy at launch index 2 so the harness's fixed ncu slot (index 3)
// lands on score_kernel
__global__ void idx_pad_kernel(){ if (threadIdx.x < 32) g_dummy[threadIdx.x] = 0.f; }

// ============================================================
// K2: fused score GEMM (fp16 m16n8k16), cp.async 3-stage
//   CTA tile 64x256, warps 2m x 4n, warp tile 32x64
//   grid (2 a-chunks, 392 m-tiles), 256 threads, 2 CTAs/SM
// ============================================================
#define MT 64
#define NT 256
#define KC 32               // k-values per chunk
#define ASTR 40             // A row stride in floats
#define BSTRW 20            // B row stride in words (16 + 4 pad)
#define ASTG (MT*ASTR)      // 2560 floats
#define BSTGW (NT*BSTRW)    // 5120 words
#define STGF (ASTG+BSTGW)   // 7680 4-byte units per stage
#define SMEM_K2 (3*STGF*4)  // 92160 B
#define NCH (E_/KC)         // 64

__global__ __launch_bounds__(256,2) void score_kernel(
    const float* __restrict__ enc, const float* __restrict__ Wf)
{
    extern __shared__ float sm[];
    const uint32_t sbase = smem_u32(sm);

    const int tid  = threadIdx.x;
    const int lane = tid & 31, warp = tid >> 5;
    const int wm = (warp >> 2) * 32;   // warp m offset (0 or 32)
    const int wn = (warp & 3) * 64;    // warp n offset (0,64,128,192)
    const int m0 = blockIdx.y * MT;
    const int a0 = blockIdx.x * NT;

    // cp.async maps
    const int ar = tid >> 3,  ak = (tid & 7) * 4;    // A: rows 0..31 (+32)
    const int bn = tid >> 1,  bw = (tid & 1) * 8;    // B: n row (+128), word off
    const float*    gA  = enc  + (size_t)(m0 + ar)*E_ + ak;
    const uint32_t* gBp = g_Wp + (size_t)(a0 + bn)*(E_/2) + bw;
    const uint32_t dA = sbase + (ar*ASTR + ak)*4;
    const uint32_t dB = sbase + (ASTG + bn*BSTRW + bw)*4;

    auto issue = [&](int c){
        const int s = c % 3;
        const uint32_t so = s*STGF*4;
        const float* pa = gA + c*KC;
        cpasync16(so + dA,              pa);
        cpasync16(so + dA + 32*ASTR*4,  pa + (size_t)32*E_);
        const uint32_t* pb = gBp + c*(KC/2);
        cpasync16(so + dB,                    pb);
        cpasync16(so + dB + 16,               pb + 4);
        cpasync16(so + dB + 128*BSTRW*4,      pb + (size_t)128*(E_/2));
        cpasync16(so + dB + 128*BSTRW*4 + 16, pb + (size_t)128*(E_/2) + 4);
        CP_COMMIT();
    };

    float acc[2][8][4];
    #pragma unroll
    for (int i=0;i<2;i++)
        #pragma unroll
        for (int j=0;j<8;j++)
            #pragma unroll
            for (int k=0;k<4;k++) acc[i][j][k] = 0.f;

    issue(0); issue(1);

    const int q = lane >> 2;      // 0..7
    const int c = lane & 3;       // 0..3

    for (int kc=0; kc<NCH; kc++){
        if (kc < NCH-2) { CP_WAIT1(); } else { CP_WAIT0(); }
        __syncthreads();
        // stage (kc+2)%3 == stage (kc-1)%3; all warps are past reading it
        if (kc < NCH-2) issue(kc+2);

        const float* cA = sm + (kc%3)*STGF;
        const uint32_t* cBw = (const uint32_t*)(cA + ASTG);
        #pragma unroll
        for (int kk=0; kk<2; kk++){
            uint32_t af[2][4], bfr[8][2];
            #pragma unroll
            for (int ms=0; ms<2; ms++){
                const float* p = cA + (wm + ms*16 + q)*ASTR + kk*16 + 2*c;
                const float2 x0 = *(const float2*)(p);
                const float2 x1 = *(const float2*)(p + 8*ASTR);
                const float2 x2 = *(const float2*)(p + 8);
                const float2 x3 = *(const float2*)(p + 8*ASTR + 8);
                af[ms][0] = pack2(x0.x, x0.y);
                af[ms][1] = pack2(x1.x, x1.y);
                af[ms][2] = pack2(x2.x, x2.y);
                af[ms][3] = pack2(x3.x, x3.y);
            }
            #pragma unroll
            for (int ns=0; ns<8; ns++){
                const uint32_t* p = cBw + (wn + ns*8 + q)*BSTRW + kk*8 + c;
                bfr[ns][0] = p[0];
                bfr[ns][1] = p[4];
            }
            #pragma unroll
            for (int ms=0; ms<2; ms++)
                #pragma unroll
                for (int ns=0; ns<8; ns++)
                    mma16(acc[ms][ns][0],acc[ms][ns][1],acc[ms][ns][2],acc[ms][ns][3],
                          af[ms][0],af[ms][1],af[ms][2],af[ms][3],
                          bfr[ns][0],bfr[ns][1]);
        }
    }

    // ---- epilogue: tanh(+c2) dot Wf, quad-reduce, write partials ----
    const int c2i = c*2;
    #pragma unroll
    for (int ms=0; ms<2; ms++){
        const int r0 = m0 + wm + ms*16 + q;
        const int r1 = r0 + 8;
        const int b0 = r0 / N_;
        const int b1 = r1 / N_;
        float s0 = 0.f, s1 = 0.f;
        #pragma unroll
        for (int ns=0; ns<8; ns++){
            const int ag = a0 + wn + ns*8 + c2i;
            const float w0 = __ldg(&Wf[ag]), w1 = __ldg(&Wf[ag+1]);
            const float c00 = g_c2[(size_t)b0*A_ + ag], c01 = g_c2[(size_t)b0*A_ + ag + 1];
            const float c10 = g_c2[(size_t)b1*A_ + ag], c11 = g_c2[(size_t)b1*A_ + ag + 1];
            s0 += tanhf(acc[ms][ns][0] + c00) * w0 + tanhf(acc[ms][ns][1] + c01) * w1;
            s1 += tanhf(acc[ms][ns][2] + c10) * w0 + tanhf(acc[ms][ns][3] + c11) * w1;
        }
        s0 += __shfl_xor_sync(0xffffffffu, s0, 1);
        s0 += __shfl_xor_sync(0xffffffffu, s0, 2);
        s1 += __shfl_xor_sync(0xffffffffu, s1, 1);
        s1 += __shfl_xor_sync(0xffffffffu, s1, 2);
        if (c == 0){
            g_sp[(size_t)r0*8 + blockIdx.x*4 + (warp & 3)] = s0;
            g_sp[(size_t)r1*8 + blockIdx.x*4 + (warp & 3)] = s1;
        }
    }
}

// ============================================================
// K3: softmax over n per batch
// ============================================================
__global__ __launch_bounds__(256) void softmax_kernel(float* __restrict__ alpha)
{
    __shared__ float sh[256];
    const int b = blockIdx.x, t = threadIdx.x;
    float val = 0.f;
    if (t < N_){
        const float* p = &g_sp[(size_t)(b*N_ + t)*8];
        #pragma unroll
        for (int j=0;j<8;j++) val += p[j];
    }
    sh[t] = (t < N_) ? val : -1e30f;
    __syncthreads();
    for (int s=128; s>0; s>>=1){
        if (t < s) sh[t] = fmaxf(sh[t], sh[t+s]);
        __syncthreads();
    }
    const float mx = sh[0];
    __syncthreads();
    const float e = (t < N_) ? expf(val - mx) : 0.f;
    sh[t] = e;
    __syncthreads();
    for (int s=128; s>0; s>>=1){
        if (t < s) sh[t] += sh[t+s];
        __syncthreads();
    }
    const float inv = 1.f / sh[0];
    if (t < N_) alpha[(size_t)b*N_ + t] = e * inv;
}

// ============================================================
// K4: context[b][e] = sum_n alpha[b][n]*enc[b][n][e]
// ============================================================
__global__ __launch_bounds__(512) void ctx_kernel(
    const float* __restrict__ enc, const float* __restrict__ alpha,
    float* __restrict__ out)
{
    __shared__ float sal[N_];
    __shared__ float4 sred[3][128];
    const int b = blockIdx.y;
    const int t = threadIdx.x;
    for (int i=t; i<N_; i+=512) sal[i] = alpha[(size_t)b*N_ + i];
    __syncthreads();

    const int col = t & 127;
    const int nq  = t >> 7;
    const float4* pe = (const float4*)(enc + (size_t)b*N_*E_ + blockIdx.x*512) + col;
    const int n0 = nq * 49, n1 = n0 + 49;
    float4 acc = {0,0,0,0};
    #pragma unroll 7
    for (int n=n0; n<n1; n++){
        const float a = sal[n];
        const float4 v = pe[(size_t)n*(E_/4)];
        acc.x += v.x*a; acc.y += v.y*a; acc.z += v.z*a; acc.w += v.w*a;
    }
    if (nq > 0) sred[nq-1][col] = acc;
    __syncthreads();
    if (nq == 0){
        #pragma unroll
        for (int j=0;j<3;j++){
            const float4 o = sred[j][col];
            acc.x += o.x; acc.y += o.y; acc.z += o.z; acc.w += o.w;
        }
        ((float4*)(out + (size_t)b*E_ + blockIdx.x*512))[col] = acc;
    }
}

// ============================================================
extern "C" void kernel_launch(void* const* d_in, const int* in_sizes, int n_in,
                              void* d_out, int out_size)
{
    (void)in_sizes; (void)n_in; (void)out_size;
    const float* enc = (const float*)d_in[0];   // (B,N,E)
    const float* dec = (const float*)d_in[1];   // (B,D)
    const float* We  = (const float*)d_in[2];   // (E,A)
    const float* be  = (const float*)d_in[3];   // (A)
    const float* Wd  = (const float*)d_in[4];   // (D,A)
    const float* bd  = (const float*)d_in[5];   // (A)
    const float* Wf  = (const float*)d_in[6];   // (A,1)
    // d_in[7] = bf : softmax-invariant, unused

    float* ctx_out   = (float*)d_out;               // (B,E)
    float* alpha_out = ctx_out + (size_t)B_*E_;     // (B,N,1)

    cudaFuncSetAttribute(score_kernel, cudaFuncAttributeMaxDynamicSharedMemorySize, SMEM_K2);

    pack_we<<<dim3(32,16), dim3(32,8)>>>(We);                 // idx 0
    att2_kernel<<<dim3(4,8), 256>>>(dec, Wd, bd, be);         // idx 1
    idx_pad_kernel<<<1, 32>>>();                              // idx 2 (pad)
    score_kernel<<<dim3(2,392), 256, SMEM_K2>>>(enc, Wf);     // idx 3 -> profiled
    softmax_kernel<<<128, 256>>>(alpha_out);                  // idx 4
    ctx_kernel<<<dim3(4,128), 512>>>(enc, alpha_out, ctx_out);// idx 5
}

// round 12
// speedup vs baseline: 1.0879x; 1.0879x over previous
#include <cuda_runtime.h>
#include <cuda_fp16.h>
#include <cstdint>
#include <cstddef>

#define B_ 128
#define N_ 196
#define E_ 2048
#define D_ 512
#define A_ 512
#define M_ (B_*N_)   // 25088

// ---- device scratch (allocation-free rule) ----
__device__ float g_c2[B_*A_];          // att2 + bd + be, [B][A]
__device__ float g_sp[M_*8];           // partial scores, 8 slices per row
__device__ uint32_t g_Wp[A_*(E_/2)];   // We packed: [n][k/2] fp16x2 (low=even k)
__device__ __half g_encH[(size_t)M_*E_]; // enc in fp16 (~102 MB)

// ---- helpers ----
__device__ __forceinline__ uint32_t pack2(float lo, float hi){
    uint32_t r; asm("cvt.rn.f16x2.f32 %0, %1, %2;" : "=r"(r) : "f"(hi), "f"(lo));
    return r;
}
__device__ __forceinline__ void mma16(float&d0,float&d1,float&d2,float&d3,
    uint32_t a0,uint32_t a1,uint32_t a2,uint32_t a3,uint32_t b0,uint32_t b1){
    asm volatile("mma.sync.aligned.m16n8k16.row.col.f32.f16.f16.f32 "
        "{%0,%1,%2,%3},{%4,%5,%6,%7},{%8,%9},{%0,%1,%2,%3};\n"
        : "+f"(d0),"+f"(d1),"+f"(d2),"+f"(d3)
        : "r"(a0),"r"(a1),"r"(a2),"r"(a3),"r"(b0),"r"(b1));
}
__device__ __forceinline__ uint32_t smem_u32(const void* p){
    uint32_t a;
    asm("{ .reg .u64 t; cvta.to.shared.u64 t, %1; cvt.u32.u64 %0, t; }" : "=r"(a) : "l"(p));
    return a;
}
__device__ __forceinline__ void cpasync16(uint32_t dst, const void* src){
    asm volatile("cp.async.cg.shared.global [%0], [%1], 16;" :: "r"(dst), "l"(src));
}
#define CP_COMMIT() asm volatile("cp.async.commit_group;" ::: "memory")
#define CP_WAIT2()  asm volatile("cp.async.wait_group 2;" ::: "memory")
#define CP_WAIT1()  asm volatile("cp.async.wait_group 1;" ::: "memory")
#define CP_WAIT0()  asm volatile("cp.async.wait_group 0;" ::: "memory")

// ============================================================
// K0a: convert enc fp32 -> g_encH fp16 (8 elems/thread)
// grid 25088 x 256
// ============================================================
__global__ __launch_bounds__(256) void conv_enc(const float* __restrict__ e)
{
    const size_t i = ((size_t)blockIdx.x*256 + threadIdx.x)*8;
    const float4 v0 = *(const float4*)(e + i);
    const float4 v1 = *(const float4*)(e + i + 4);
    uint4 o;
    o.x = pack2(v0.x, v0.y); o.y = pack2(v0.z, v0.w);
    o.z = pack2(v1.x, v1.y); o.w = pack2(v1.z, v1.w);
    *(uint4*)(g_encH + i) = o;
}

// ============================================================
// K0b: pack We [E][A] fp32 -> g_Wp [A][E/2] fp16x2 (k-pairs)
// ============================================================
__global__ __launch_bounds__(256) void pack_we(const float* __restrict__ We)
{
    __shared__ float s[64][33];
    const int k0 = blockIdx.x * 64, n0 = blockIdx.y * 32;
    const int tx = threadIdx.x, ty = threadIdx.y;
    #pragma unroll
    for (int j = ty; j < 64; j += 8)
        s[j][tx] = We[(size_t)(k0 + j)*A_ + n0 + tx];
    __syncthreads();
    const int kp0 = blockIdx.x * 32;
    #pragma unroll
    for (int j = ty; j < 32; j += 8)
        g_Wp[(size_t)(n0 + j)*(E_/2) + kp0 + tx] = pack2(s[2*tx][j], s[2*tx+1][j]);
}

// ============================================================
// K1: g_c2[b][a] = dec[b]@Wd[:,a] + bd[a] + be[a]
// ============================================================
__global__ __launch_bounds__(256) void att2_kernel(
    const float* __restrict__ dec, const float* __restrict__ Wd,
    const float* __restrict__ bd,  const float* __restrict__ be)
{
    __shared__ float sDec[16*D_];
    const int tid = threadIdx.x;
    const int a0 = blockIdx.x*128, b0 = blockIdx.y*16;

    const float4* src = (const float4*)(dec + (size_t)b0*D_);
    float4* dst = (float4*)sDec;
    for (int i=tid; i<16*D_/4; i+=256) dst[i] = src[i];
    __syncthreads();

    const int tx = tid & 31, ty = tid >> 5;
    const float4* wp = (const float4*)(Wd + a0) + tx;
    float4 acc0 = {0,0,0,0}, acc1 = {0,0,0,0};
    for (int d=0; d<D_; d++){
        float4 w = wp[(size_t)d*(A_/4)];
        float x0 = sDec[ty*D_ + d];
        float x1 = sDec[(ty+8)*D_ + d];
        acc0.x += w.x*x0; acc0.y += w.y*x0; acc0.z += w.z*x0; acc0.w += w.w*x0;
        acc1.x += w.x*x1; acc1.y += w.y*x1; acc1.z += w.z*x1; acc1.w += w.w*x1;
    }
    const int a = a0 + tx*4;
    float bx = bd[a]   + be[a];
    float by = bd[a+1] + be[a+1];
    float bz = bd[a+2] + be[a+2];
    float bw = bd[a+3] + be[a+3];
    float4 o0 = {acc0.x+bx, acc0.y+by, acc0.z+bz, acc0.w+bw};
    float4 o1 = {acc1.x+bx, acc1.y+by, acc1.z+bz, acc1.w+bw};
    *(float4*)&g_c2[(size_t)(b0+ty  )*A_ + a] = o0;
    *(float4*)&g_c2[(size_t)(b0+ty+8)*A_ + a] = o1;
}

// ============================================================
// K2: fused score GEMM (fp16 m16n8k16), cp.async 4-stage, A fp16
//   CTA tile 128x128, warps 4m x 2n, warp tile 32x64
//   grid (4 a-chunks, 196 m-tiles), 256 threads, 2 CTAs/SM
// ============================================================
#define MT 128
#define NT 128
#define KC 32                 // k-values per chunk
#define ASTRH 40              // A row stride in halves (80 B; LDS.32 conflict-free)
#define BSTRW 20              // B row stride in words (16 + 4 pad)
#define ABYTES (MT*ASTRH*2)   // 10240 B
#define BBYTES (NT*BSTRW*4)   // 10240 B
#define STGB (ABYTES+BBYTES)  // 20480 B per stage
#define SMEM_K2 (4*STGB)      // 81920 B
#define NCH (E_/KC)           // 64

__global__ __launch_bounds__(256,2) void score_kernel(const float* __restrict__ Wf)
{
    extern __shared__ __align__(16) char smem[];
    const uint32_t sbase = smem_u32(smem);

    const int tid  = threadIdx.x;
    const int lane = tid & 31, warp = tid >> 5;
    const int wm = (warp >> 1) * 32;   // warp m offset (0,32,64,96)
    const int wn = (warp & 1) * 64;    // warp n offset (0 or 64)
    const int m0 = blockIdx.y * MT;
    const int a0 = blockIdx.x * NT;

    // cp.async maps
    const int arr = tid >> 2, ah = (tid & 3) * 8;    // A: rows 0..63 (+64), half-off
    const int bn  = tid >> 1, bw = (tid & 1) * 8;    // B: n row, word-off
    const __half*   gAh = g_encH + (size_t)(m0 + arr)*E_ + ah;
    const uint32_t* gBp = g_Wp   + (size_t)(a0 + bn)*(E_/2) + bw;
    const uint32_t dA = sbase + arr*(ASTRH*2) + (tid & 3)*16;
    const uint32_t dB = sbase + ABYTES + (bn*BSTRW + bw)*4;

    auto issue = [&](int cc){
        const uint32_t so = (cc & 3)*STGB;
        const __half* pa = gAh + cc*KC;
        cpasync16(so + dA,                 pa);
        cpasync16(so + dA + 64*ASTRH*2,    pa + (size_t)64*E_);
        const uint32_t* pb = gBp + cc*(KC/2);
        cpasync16(so + dB,      pb);
        cpasync16(so + dB + 16, pb + 4);
        CP_COMMIT();
    };

    float acc[2][8][4];
    #pragma unroll
    for (int i=0;i<2;i++)
        #pragma unroll
        for (int j=0;j<8;j++)
            #pragma unroll
            for (int k=0;k<4;k++) acc[i][j][k] = 0.f;

    issue(0); issue(1); issue(2);

    const int q = lane >> 2;      // 0..7
    const int c = lane & 3;       // 0..3

    for (int kc=0; kc<NCH; kc++){
        if (kc <= NCH-3)      { CP_WAIT2(); }
        else if (kc == NCH-2) { CP_WAIT1(); }
        else                  { CP_WAIT0(); }
        __syncthreads();
        // stage (kc+3)%4 == stage (kc-1)%4; all warps are past reading it
        if (kc < NCH-3) issue(kc+3);

        const char* stg = smem + (kc & 3)*STGB;
        const __half*   cA  = (const __half*)stg;
        const uint32_t* cBw = (const uint32_t*)(stg + ABYTES);
        #pragma unroll
        for (int kk=0; kk<2; kk++){
            uint32_t af[2][4], bfr[8][2];
            #pragma unroll
            for (int ms=0; ms<2; ms++){
                const __half* p = cA + (wm + ms*16 + q)*ASTRH + kk*16 + 2*c;
                af[ms][0] = *(const uint32_t*)(p);
                af[ms][1] = *(const uint32_t*)(p + 8*ASTRH);
                af[ms][2] = *(const uint32_t*)(p + 8);
                af[ms][3] = *(const uint32_t*)(p + 8*ASTRH + 8);
            }
            #pragma unroll
            for (int ns=0; ns<8; ns++){
                const uint32_t* p = cBw + (wn + ns*8 + q)*BSTRW + kk*8 + c;
                bfr[ns][0] = p[0];
                bfr[ns][1] = p[4];
            }
            #pragma unroll
            for (int ms=0; ms<2; ms++)
                #pragma unroll
                for (int ns=0; ns<8; ns++)
                    mma16(acc[ms][ns][0],acc[ms][ns][1],acc[ms][ns][2],acc[ms][ns][3],
                          af[ms][0],af[ms][1],af[ms][2],af[ms][3],
                          bfr[ns][0],bfr[ns][1]);
        }
    }

    // ---- epilogue: tanh(+c2) dot Wf, quad-reduce, write partials ----
    const int c2i = c*2;
    #pragma unroll
    for (int ms=0; ms<2; ms++){
        const int r0 = m0 + wm + ms*16 + q;
        const int r1 = r0 + 8;
        const int b0 = r0 / N_;
        const int b1 = r1 / N_;
        float s0 = 0.f, s1 = 0.f;
        #pragma unroll
        for (int ns=0; ns<8; ns++){
            const int ag = a0 + wn + ns*8 + c2i;
            const float w0 = __ldg(&Wf[ag]), w1 = __ldg(&Wf[ag+1]);
            const float c00 = g_c2[(size_t)b0*A_ + ag], c01 = g_c2[(size_t)b0*A_ + ag + 1];
            const float c10 = g_c2[(size_t)b1*A_ + ag], c11 = g_c2[(size_t)b1*A_ + ag + 1];
            s0 += tanhf(acc[ms][ns][0] + c00) * w0 + tanhf(acc[ms][ns][1] + c01) * w1;
            s1 += tanhf(acc[ms][ns][2] + c10) * w0 + tanhf(acc[ms][ns][3] + c11) * w1;
        }
        s0 += __shfl_xor_sync(0xffffffffu, s0, 1);
        s0 += __shfl_xor_sync(0xffffffffu, s0, 2);
        s1 += __shfl_xor_sync(0xffffffffu, s1, 1);
        s1 += __shfl_xor_sync(0xffffffffu, s1, 2);
        if (c == 0){
            g_sp[(size_t)r0*8 + blockIdx.x*2 + (warp & 1)] = s0;
            g_sp[(size_t)r1*8 + blockIdx.x*2 + (warp & 1)] = s1;
        }
    }
}

// ============================================================
// K3: softmax over n per batch
// ============================================================
__global__ __launch_bounds__(256) void softmax_kernel(float* __restrict__ alpha)
{
    __shared__ float sh[256];
    const int b = blockIdx.x, t = threadIdx.x;
    float val = 0.f;
    if (t < N_){
        const float* p = &g_sp[(size_t)(b*N_ + t)*8];
        #pragma unroll
        for (int j=0;j<8;j++) val += p[j];
    }
    sh[t] = (t < N_) ? val : -1e30f;
    __syncthreads();
    for (int s=128; s>0; s>>=1){
        if (t < s) sh[t] = fmaxf(sh[t], sh[t+s]);
        __syncthreads();
    }
    const float mx = sh[0];
    __syncthreads();
    const float e = (t < N_) ? expf(val - mx) : 0.f;
    sh[t] = e;
    __syncthreads();
    for (int s=128; s>0; s>>=1){
        if (t < s) sh[t] += sh[t+s];
        __syncthreads();
    }
    const float inv = 1.f / sh[0];
    if (t < N_) alpha[(size_t)b*N_ + t] = e * inv;
}

// ============================================================
// K4: context[b][e] = sum_n alpha[b][n]*enc_h[b][n][e]  (fp16 enc)
// block 512: 4-way n-split + smem combine; 4 halves per thread
// ============================================================
__global__ __launch_bounds__(512) void ctx_kernel(
    const float* __restrict__ alpha, float* __restrict__ out)
{
    __shared__ float sal[N_];
    __shared__ float4 sred[3][128];
    const int b = blockIdx.y;
    const int t = threadIdx.x;
    for (int i=t; i<N_; i+=512) sal[i] = alpha[(size_t)b*N_ + i];
    __syncthreads();

    const int col = t & 127;       // 4-half column within 512-wide chunk
    const int nq  = t >> 7;        // n-quarter 0..3
    const uint2* pe = (const uint2*)(g_encH + (size_t)b*N_*E_ + blockIdx.x*512) + col;
    const int n0 = nq * 49, n1 = n0 + 49;
    float4 acc = {0,0,0,0};
    #pragma unroll 7
    for (int n=n0; n<n1; n++){
        const float a = sal[n];
        const uint2 v = pe[(size_t)n*(E_/4)];
        const float2 f0 = __half22float2(*(const __half2*)&v.x);
        const float2 f1 = __half22float2(*(const __half2*)&v.y);
        acc.x += f0.x*a; acc.y += f0.y*a; acc.z += f1.x*a; acc.w += f1.y*a;
    }
    if (nq > 0) sred[nq-1][col] = acc;
    __syncthreads();
    if (nq == 0){
        #pragma unroll
        for (int j=0;j<3;j++){
            const float4 o = sred[j][col];
            acc.x += o.x; acc.y += o.y; acc.z += o.z; acc.w += o.w;
        }
        ((float4*)(out + (size_t)b*E_ + blockIdx.x*512))[col] = acc;
    }
}

// ============================================================
extern "C" void kernel_launch(void* const* d_in, const int* in_sizes, int n_in,
                              void* d_out, int out_size)
{
    (void)in_sizes; (void)n_in; (void)out_size;
    const float* enc = (const float*)d_in[0];   // (B,N,E)
    const float* dec = (const float*)d_in[1];   // (B,D)
    const float* We  = (const float*)d_in[2];   // (E,A)
    const float* be  = (const float*)d_in[3];   // (A)
    const float* Wd  = (const float*)d_in[4];   // (D,A)
    const float* bd  = (const float*)d_in[5];   // (A)
    const float* Wf  = (const float*)d_in[6];   // (A,1)
    // d_in[7] = bf : softmax-invariant, unused

    float* ctx_out   = (float*)d_out;               // (B,E)
    float* alpha_out = ctx_out + (size_t)B_*E_;     // (B,N,1)

    cudaFuncSetAttribute(score_kernel, cudaFuncAttributeMaxDynamicSharedMemorySize, SMEM_K2);

    conv_enc<<<(int)(((size_t)M_*E_)/(256*8)), 256>>>(enc);   // idx 0
    pack_we<<<dim3(32,16), dim3(32,8)>>>(We);                 // idx 1
    att2_kernel<<<dim3(4,8), 256>>>(dec, Wd, bd, be);         // idx 2
    score_kernel<<<dim3(4,196), 256, SMEM_K2>>>(Wf);          // idx 3 -> profiled
    softmax_kernel<<<128, 256>>>(alpha_out);                  // idx 4
    ctx_kernel<<<dim3(4,128), 512>>>(alpha_out, ctx_out);     // idx 5
}

// round 14
// speedup vs baseline: 1.2616x; 1.1597x over previous
#include <cuda_runtime.h>
#include <cuda_fp16.h>
#include <cstdint>
#include <cstddef>

#define B_ 128
#define N_ 196
#define E_ 2048
#define D_ 512
#define A_ 512
#define M_ (B_*N_)   // 25088

// ---- device scratch (allocation-free rule) ----
__device__ float g_c2[B_*A_];            // att2 + bd + be, [B][A]
__device__ float g_sp[M_*8];             // partial scores, 8 slices per row
__device__ uint32_t g_Wp[A_*(E_/2)];     // We packed fp16x2, words B-permuted
__device__ __half g_encP[(size_t)M_*E_]; // enc fp16, halves A-permuted (~102 MB)

// Permutations (within each 32-k chunk):
//  A halves, per 16-half group: new[4c+2h+b] = old[2(4h+c)+b]
//    -> new pos 4c..4c+3 hold old halves (2c,2c+1,2c+8,2c+9)
//  B words, per 16-word group (one chunk): new[4c+j] = old[c+4j]
//    -> LDS.128 at 4c gives (kk0 b0, kk0 b1, kk1 b0, kk1 b1)

// ---- helpers ----
__device__ __forceinline__ uint32_t pack2(float lo, float hi){
    uint32_t r; asm("cvt.rn.f16x2.f32 %0, %1, %2;" : "=r"(r) : "f"(hi), "f"(lo));
    return r;
}
__device__ __forceinline__ void mma16(float&d0,float&d1,float&d2,float&d3,
    uint32_t a0,uint32_t a1,uint32_t a2,uint32_t a3,uint32_t b0,uint32_t b1){
    asm volatile("mma.sync.aligned.m16n8k16.row.col.f32.f16.f16.f32 "
        "{%0,%1,%2,%3},{%4,%5,%6,%7},{%8,%9},{%0,%1,%2,%3};\n"
        : "+f"(d0),"+f"(d1),"+f"(d2),"+f"(d3)
        : "r"(a0),"r"(a1),"r"(a2),"r"(a3),"r"(b0),"r"(b1));
}
__device__ __forceinline__ uint32_t smem_u32(const void* p){
    uint32_t a;
    asm("{ .reg .u64 t; cvta.to.shared.u64 t, %1; cvt.u32.u64 %0, t; }" : "=r"(a) : "l"(p));
    return a;
}
__device__ __forceinline__ void cpasync16(uint32_t dst, const void* src){
    asm volatile("cp.async.cg.shared.global [%0], [%1], 16;" :: "r"(dst), "l"(src));
}
#define CP_COMMIT() asm volatile("cp.async.commit_group;" ::: "memory")
#define CP_WAIT2()  asm volatile("cp.async.wait_group 2;" ::: "memory")
#define CP_WAIT1()  asm volatile("cp.async.wait_group 1;" ::: "memory")
#define CP_WAIT0()  asm volatile("cp.async.wait_group 0;" ::: "memory")

// ============================================================
// K0a: enc fp32 -> g_encP fp16, A-permuted. 16 elems/thread.
// grid 12544 x 256
// ============================================================
__global__ __launch_bounds__(256) void conv_enc(const float* __restrict__ e)
{
    const size_t i = ((size_t)blockIdx.x*256 + threadIdx.x)*16;
    float f[16];
    #pragma unroll
    for (int j=0;j<4;j++) *(float4*)(f+4*j) = *(const float4*)(e + i + 4*j);
    uint4 o0, o1;
    o0.x = pack2(f[0],f[1]);   o0.y = pack2(f[8],f[9]);
    o0.z = pack2(f[2],f[3]);   o0.w = pack2(f[10],f[11]);
    o1.x = pack2(f[4],f[5]);   o1.y = pack2(f[12],f[13]);
    o1.z = pack2(f[6],f[7]);   o1.w = pack2(f[14],f[15]);
    *(uint4*)(g_encP + i)     = o0;
    *(uint4*)(g_encP + i + 8) = o1;
}

// ============================================================
// K0b: We [E][A] fp32 -> g_Wp [n][1024 words], B-permuted
// ============================================================
__global__ __launch_bounds__(256) void pack_we(const float* __restrict__ We)
{
    __shared__ float s[64][33];
    const int k0 = blockIdx.x * 64, n0 = blockIdx.y * 32;
    const int tx = threadIdx.x, ty = threadIdx.y;
    #pragma unroll
    for (int j = ty; j < 64; j += 8)
        s[j][tx] = We[(size_t)(k0 + j)*A_ + n0 + tx];
    __syncthreads();
    const int kp0 = blockIdx.x * 32;   // source pair base
    #pragma unroll
    for (int j = ty; j < 32; j += 8){
        #pragma unroll
        for (int g = 0; g < 1; g++){}  // (no-op; clarity)
        // tx enumerates source pair within the 32-pair block
        const int grp = tx >> 4, w = tx & 15;
        const int dst = kp0 + grp*16 + 4*(w & 3) + (w >> 2);
        g_Wp[(size_t)(n0 + j)*(E_/2) + dst] = pack2(s[2*tx][j], s[2*tx+1][j]);
    }
}

// ============================================================
// K1: g_c2[b][a] = dec[b]@Wd[:,a] + bd[a] + be[a]
// grid (16 a-chunks of 32, 16 b-chunks of 8), 256 thr, D split 4
// ============================================================
__global__ __launch_bounds__(256) void att2_kernel(
    const float* __restrict__ dec, const float* __restrict__ Wd,
    const float* __restrict__ bd,  const float* __restrict__ be)
{
    __shared__ float sDec[8*D_];
    __shared__ float4 sred[256];
    const int tid = threadIdx.x;
    const int a0 = blockIdx.x*32, b0 = blockIdx.y*8;

    const float4* src = (const float4*)(dec + (size_t)b0*D_);
    for (int i=tid; i<8*D_/4; i+=256) ((float4*)sDec)[i] = src[i];
    __syncthreads();

    const int tx = tid & 7;            // a: 8 x float4 = 32
    const int tg = tid >> 3;           // 0..31
    const int bl = tg & 7;             // b row
    const int ds = tg >> 3;            // D quarter 0..3
    const float4* wp = (const float4*)(Wd + a0) + tx;
    float4 acc = {0,0,0,0};
    const int d0 = ds*128, d1 = d0+128;
    for (int d=d0; d<d1; d++){
        const float4 w = wp[(size_t)d*(A_/4)];
        const float x = sDec[bl*D_ + d];
        acc.x += w.x*x; acc.y += w.y*x; acc.z += w.z*x; acc.w += w.w*x;
    }
    sred[tid] = acc;
    __syncthreads();
    if (ds == 0){
        #pragma unroll
        for (int j=1;j<4;j++){
            const float4 o = sred[tid + j*64];
            acc.x += o.x; acc.y += o.y; acc.z += o.z; acc.w += o.w;
        }
        const int a = a0 + tx*4;
        acc.x += bd[a]   + be[a];
        acc.y += bd[a+1] + be[a+1];
        acc.z += bd[a+2] + be[a+2];
        acc.w += bd[a+3] + be[a+3];
        *(float4*)&g_c2[(size_t)(b0+bl)*A_ + a] = acc;
    }
}

// ============================================================
// K2: fused score GEMM (fp16 m16n8k16), cp.async 4-stage,
//     permuted layouts -> LDS.128 (B) / LDS.64 (A)
//   CTA 128x128, warps 4m x 2n, warp tile 32x64
//   grid (4 a-chunks, 196 m-tiles), 256 threads, 2 CTAs/SM
// ============================================================
#define MT 128
#define NT 128
#define KC 32
#define ASTRB 96              // A row stride bytes (64 data + 32 pad)
#define BSTRB 64              // B row stride bytes (16 words, no pad)
#define ABYTES (MT*ASTRB)     // 12288
#define BBYTES (NT*BSTRB)     // 8192
#define STGB (ABYTES+BBYTES)  // 20480
#define SMEM_K2 (4*STGB)      // 81920
#define NCH (E_/KC)           // 64

__global__ __launch_bounds__(256,2) void score_kernel(const float* __restrict__ Wf)
{
    extern __shared__ __align__(16) char smem[];
    const uint32_t sbase = smem_u32(smem);

    const int tid  = threadIdx.x;
    const int lane = tid & 31, warp = tid >> 5;
    const int wm = (warp >> 1) * 32;   // warp m offset (0,32,64,96)
    const int wn = (warp & 1) * 64;    // warp n offset (0 or 64)
    const int m0 = blockIdx.y * MT;
    const int a0 = blockIdx.x * NT;

    // cp.async maps: 2 threads per row, 32B each, for both A and B
    const int ar = tid >> 1, hh = tid & 1;
    const __half*   gAh = g_encP + (size_t)(m0 + ar)*E_ + hh*16;
    const uint32_t* gBp = g_Wp   + (size_t)(a0 + ar)*(E_/2) + hh*8;
    const uint32_t dA = sbase + ar*ASTRB + hh*32;
    const uint32_t dB = sbase + ABYTES + ar*BSTRB + hh*32;

    auto issue = [&](int cc){
        const uint32_t so = (cc & 3)*STGB;
        const __half* pa = gAh + cc*KC;
        cpasync16(so + dA,      pa);
        cpasync16(so + dA + 16, pa + 8);
        const uint32_t* pb = gBp + cc*(KC/2);
        cpasync16(so + dB,      pb);
        cpasync16(so + dB + 16, pb + 4);
        CP_COMMIT();
    };

    float acc[2][8][4];
    #pragma unroll
    for (int i=0;i<2;i++)
        #pragma unroll
        for (int j=0;j<8;j++)
            #pragma unroll
            for (int k=0;k<4;k++) acc[i][j][k] = 0.f;

    issue(0); issue(1); issue(2);

    const int q = lane >> 2;      // 0..7
    const int c = lane & 3;       // 0..3

    for (int kc=0; kc<NCH; kc++){
        if (kc <= NCH-3)      { CP_WAIT2(); }
        else if (kc == NCH-2) { CP_WAIT1(); }
        else                  { CP_WAIT0(); }
        __syncthreads();
        if (kc < NCH-3) issue(kc+3);

        const char* stg = smem + (kc & 3)*STGB;
        const char* cA  = stg;
        const char* cB  = stg + ABYTES;

        // B: one LDS.128 per ns covers both kk
        uint4 bq[8];
        #pragma unroll
        for (int ns=0; ns<8; ns++)
            bq[ns] = *(const uint4*)(cB + (wn + ns*8 + q)*BSTRB + 16*c);

        #pragma unroll
        for (int kk=0; kk<2; kk++){
            uint32_t af[2][4];
            #pragma unroll
            for (int ms=0; ms<2; ms++){
                const char* pr = cA + (wm + ms*16 + q)*ASTRB + kk*32 + 8*c;
                const uint2 lo = *(const uint2*)(pr);
                const uint2 hi = *(const uint2*)(pr + 8*ASTRB);
                af[ms][0] = lo.x; af[ms][1] = hi.x;
                af[ms][2] = lo.y; af[ms][3] = hi.y;
            }
            #pragma unroll
            for (int ms=0; ms<2; ms++)
                #pragma unroll
                for (int ns=0; ns<8; ns++){
                    const uint32_t b0r = kk ? bq[ns].z : bq[ns].x;
                    const uint32_t b1r = kk ? bq[ns].w : bq[ns].y;
                    mma16(acc[ms][ns][0],acc[ms][ns][1],acc[ms][ns][2],acc[ms][ns][3],
                          af[ms][0],af[ms][1],af[ms][2],af[ms][3], b0r, b1r);
                }
        }
    }

    // ---- epilogue: tanh(+c2) dot Wf, quad-reduce, write partials ----
    const int c2i = c*2;
    #pragma unroll
    for (int ms=0; ms<2; ms++){
        const int r0 = m0 + wm + ms*16 + q;
        const int r1 = r0 + 8;
        const int b0 = r0 / N_;
        const int b1 = r1 / N_;
        float s0 = 0.f, s1 = 0.f;
        #pragma unroll
        for (int ns=0; ns<8; ns++){
            const int ag = a0 + wn + ns*8 + c2i;
            const float w0 = __ldg(&Wf[ag]), w1 = __ldg(&Wf[ag+1]);
            const float c00 = g_c2[(size_t)b0*A_ + ag], c01 = g_c2[(size_t)b0*A_ + ag + 1];
            const float c10 = g_c2[(size_t)b1*A_ + ag], c11 = g_c2[(size_t)b1*A_ + ag + 1];
            s0 += tanhf(acc[ms][ns][0] + c00) * w0 + tanhf(acc[ms][ns][1] + c01) * w1;
            s1 += tanhf(acc[ms][ns][2] + c10) * w0 + tanhf(acc[ms][ns][3] + c11) * w1;
        }
        s0 += __shfl_xor_sync(0xffffffffu, s0, 1);
        s0 += __shfl_xor_sync(0xffffffffu, s0, 2);
        s1 += __shfl_xor_sync(0xffffffffu, s1, 1);
        s1 += __shfl_xor_sync(0xffffffffu, s1, 2);
        if (c == 0){
            g_sp[(size_t)r0*8 + blockIdx.x*2 + (warp & 1)] = s0;
            g_sp[(size_t)r1*8 + blockIdx.x*2 + (warp & 1)] = s1;
        }
    }
}

// ============================================================
// K3: softmax over n per batch
// ============================================================
__global__ __launch_bounds__(256) void softmax_kernel(float* __restrict__ alpha)
{
    __shared__ float sh[256];
    const int b = blockIdx.x, t = threadIdx.x;
    float val = 0.f;
    if (t < N_){
        const float* p = &g_sp[(size_t)(b*N_ + t)*8];
        #pragma unroll
        for (int j=0;j<8;j++) val += p[j];
    }
    sh[t] = (t < N_) ? val : -1e30f;
    __syncthreads();
    for (int s=128; s>0; s>>=1){
        if (t < s) sh[t] = fmaxf(sh[t], sh[t+s]);
        __syncthreads();
    }
    const float mx = sh[0];
    __syncthreads();
    const float e = (t < N_) ? expf(val - mx) : 0.f;
    sh[t] = e;
    __syncthreads();
    for (int s=128; s>0; s>>=1){
        if (t < s) sh[t] += sh[t+s];
        __syncthreads();
    }
    const float inv = 1.f / sh[0];
    if (t < N_) alpha[(size_t)b*N_ + t] = e * inv;
}

// ============================================================
// K4: context from permuted fp16 enc; writes de-permuted
// block 512: 4-way n-split + smem combine
// ============================================================
__global__ __launch_bounds__(512) void ctx_kernel(
    const float* __restrict__ alpha, float* __restrict__ out)
{
    __shared__ float sal[N_];
    __shared__ float4 sred[3][128];
    const int b = blockIdx.y;
    const int t = threadIdx.x;
    for (int i=t; i<N_; i+=512) sal[i] = alpha[(size_t)b*N_ + i];
    __syncthreads();

    const int col = t & 127;       // uint2 (4 permuted halves) within 512 chunk
    const int nq  = t >> 7;        // n-quarter 0..3
    const uint2* pe = (const uint2*)(g_encP + (size_t)b*N_*E_ + blockIdx.x*512) + col;
    const int n0 = nq * 49, n1 = n0 + 49;
    float4 acc = {0,0,0,0};
    #pragma unroll 7
    for (int n=n0; n<n1; n++){
        const float a = sal[n];
        const uint2 v = pe[(size_t)n*(E_/4)];
        const float2 f0 = __half22float2(*(const __half2*)&v.x);
        const float2 f1 = __half22float2(*(const __half2*)&v.y);
        acc.x += f0.x*a; acc.y += f0.y*a; acc.z += f1.x*a; acc.w += f1.y*a;
    }
    if (nq > 0) sred[nq-1][col] = acc;
    __syncthreads();
    if (nq == 0){
        #pragma unroll
        for (int j=0;j<3;j++){
            const float4 o = sred[j][col];
            acc.x += o.x; acc.y += o.y; acc.z += o.z; acc.w += o.w;
        }
        // permuted halves [4i..4i+3] of group g = old e (2i,2i+1,2i+8,2i+9)
        const int g = col >> 2, idx = col & 3;
        const int e0 = blockIdx.x*512 + g*16 + 2*idx;
        float* ob = out + (size_t)b*E_;
        *(float2*)(ob + e0)     = make_float2(acc.x, acc.y);
        *(float2*)(ob + e0 + 8) = make_float2(acc.z, acc.w);
    }
}

// ============================================================
extern "C" void kernel_launch(void* const* d_in, const int* in_sizes, int n_in,
                              void* d_out, int out_size)
{
    (void)in_sizes; (void)n_in; (void)out_size;
    const float* enc = (const float*)d_in[0];   // (B,N,E)
    const float* dec = (const float*)d_in[1];   // (B,D)
    const float* We  = (const float*)d_in[2];   // (E,A)
    const float* be  = (const float*)d_in[3];   // (A)
    const float* Wd  = (const float*)d_in[4];   // (D,A)
    const float* bd  = (const float*)d_in[5];   // (A)
    const float* Wf  = (const float*)d_in[6];   // (A,1)
    // d_in[7] = bf : softmax-invariant, unused

    float* ctx_out   = (float*)d_out;               // (B,E)
    float* alpha_out = ctx_out + (size_t)B_*E_;     // (B,N,1)

    cudaFuncSetAttribute(score_kernel, cudaFuncAttributeMaxDynamicSharedMemorySize, SMEM_K2);

    conv_enc<<<(int)(((size_t)M_*E_)/(256*16)), 256>>>(enc);  // idx 0
    pack_we<<<dim3(32,16), dim3(32,8)>>>(We);                 // idx 1
    att2_kernel<<<dim3(16,16), 256>>>(dec, Wd, bd, be);       // idx 2
    score_kernel<<<dim3(4,196), 256, SMEM_K2>>>(Wf);          // idx 3 -> profiled
    softmax_kernel<<<128, 256>>>(alpha_out);                  // idx 4
    ctx_kernel<<<dim3(4,128), 512>>>(alpha_out, ctx_out);     // idx 5
}

// round 15
// speedup vs baseline: 1.2723x; 1.0085x over previous
#include <cuda_runtime.h>
#include <cuda_fp16.h>
#include <cstdint>
#include <cstddef>

#define B_ 128
#define N_ 196
#define E_ 2048
#define D_ 512
#define A_ 512
#define M_ (B_*N_)   // 25088

// ---- device scratch (allocation-free rule) ----
__device__ float g_c2[B_*A_];            // att2 + bd + be, [B][A]
__device__ float g_sp[M_*16];            // partial scores, 16 slices per row
__device__ uint32_t g_Wp[A_*(E_/2)];     // We packed fp16x2, words B-permuted
__device__ __half g_encP[(size_t)M_*E_]; // enc fp16, halves A-permuted (~102 MB)

// Permutations (within each 32-k chunk):
//  A halves, per 16-half group: new pos 4c..4c+3 hold old halves (2c,2c+1,2c+8,2c+9)
//  B words, per 16-word group: new[4c+j] = old[c+4j]
//    -> LDS.128 at 16c bytes gives (kk0 b0, kk0 b1, kk1 b0, kk1 b1)

// ---- helpers ----
__device__ __forceinline__ uint32_t pack2(float lo, float hi){
    uint32_t r; asm("cvt.rn.f16x2.f32 %0, %1, %2;" : "=r"(r) : "f"(hi), "f"(lo));
    return r;
}
__device__ __forceinline__ void mma16(float&d0,float&d1,float&d2,float&d3,
    uint32_t a0,uint32_t a1,uint32_t a2,uint32_t a3,uint32_t b0,uint32_t b1){
    asm volatile("mma.sync.aligned.m16n8k16.row.col.f32.f16.f16.f32 "
        "{%0,%1,%2,%3},{%4,%5,%6,%7},{%8,%9},{%0,%1,%2,%3};\n"
        : "+f"(d0),"+f"(d1),"+f"(d2),"+f"(d3)
        : "r"(a0),"r"(a1),"r"(a2),"r"(a3),"r"(b0),"r"(b1));
}
__device__ __forceinline__ uint32_t smem_u32(const void* p){
    uint32_t a;
    asm("{ .reg .u64 t; cvta.to.shared.u64 t, %1; cvt.u32.u64 %0, t; }" : "=r"(a) : "l"(p));
    return a;
}
__device__ __forceinline__ void cpasync16(uint32_t dst, const void* src){
    asm volatile("cp.async.cg.shared.global [%0], [%1], 16;" :: "r"(dst), "l"(src));
}
#define CP_COMMIT() asm volatile("cp.async.commit_group;" ::: "memory")
#define CP_WAIT2()  asm volatile("cp.async.wait_group 2;" ::: "memory")
#define CP_WAIT1()  asm volatile("cp.async.wait_group 1;" ::: "memory")
#define CP_WAIT0()  asm volatile("cp.async.wait_group 0;" ::: "memory")

// ============================================================
// K0a: enc fp32 -> g_encP fp16, A-permuted. 16 elems/thread.
// ============================================================
__global__ __launch_bounds__(256) void conv_enc(const float* __restrict__ e)
{
    const size_t i = ((size_t)blockIdx.x*256 + threadIdx.x)*16;
    float f[16];
    #pragma unroll
    for (int j=0;j<4;j++) *(float4*)(f+4*j) = *(const float4*)(e + i + 4*j);
    uint4 o0, o1;
    o0.x = pack2(f[0],f[1]);   o0.y = pack2(f[8],f[9]);
    o0.z = pack2(f[2],f[3]);   o0.w = pack2(f[10],f[11]);
    o1.x = pack2(f[4],f[5]);   o1.y = pack2(f[12],f[13]);
    o1.z = pack2(f[6],f[7]);   o1.w = pack2(f[14],f[15]);
    *(uint4*)(g_encP + i)     = o0;
    *(uint4*)(g_encP + i + 8) = o1;
}

// ============================================================
// K0b: We [E][A] fp32 -> g_Wp [n][1024 words], B-permuted
// ============================================================
__global__ __launch_bounds__(256) void pack_we(const float* __restrict__ We)
{
    __shared__ float s[64][33];
    const int k0 = blockIdx.x * 64, n0 = blockIdx.y * 32;
    const int tx = threadIdx.x, ty = threadIdx.y;
    #pragma unroll
    for (int j = ty; j < 64; j += 8)
        s[j][tx] = We[(size_t)(k0 + j)*A_ + n0 + tx];
    __syncthreads();
    const int kp0 = blockIdx.x * 32;   // source pair base
    #pragma unroll
    for (int j = ty; j < 32; j += 8){
        const int grp = tx >> 4, w = tx & 15;
        const int dst = kp0 + grp*16 + 4*(w & 3) + (w >> 2);
        g_Wp[(size_t)(n0 + j)*(E_/2) + dst] = pack2(s[2*tx][j], s[2*tx+1][j]);
    }
}

// ============================================================
// K1: g_c2[b][a] = dec[b]@Wd[:,a] + bd[a] + be[a]
// ============================================================
__global__ __launch_bounds__(256) void att2_kernel(
    const float* __restrict__ dec, const float* __restrict__ Wd,
    const float* __restrict__ bd,  const float* __restrict__ be)
{
    __shared__ float sDec[8*D_];
    __shared__ float4 sred[256];
    const int tid = threadIdx.x;
    const int a0 = blockIdx.x*32, b0 = blockIdx.y*8;

    const float4* src = (const float4*)(dec + (size_t)b0*D_);
    for (int i=tid; i<8*D_/4; i+=256) ((float4*)sDec)[i] = src[i];
    __syncthreads();

    const int tx = tid & 7;            // a: 8 x float4 = 32
    const int tg = tid >> 3;           // 0..31
    const int bl = tg & 7;             // b row
    const int ds = tg >> 3;            // D quarter 0..3
    const float4* wp = (const float4*)(Wd + a0) + tx;
    float4 acc = {0,0,0,0};
    const int d0 = ds*128, d1 = d0+128;
    for (int d=d0; d<d1; d++){
        const float4 w = wp[(size_t)d*(A_/4)];
        const float x = sDec[bl*D_ + d];
        acc.x += w.x*x; acc.y += w.y*x; acc.z += w.z*x; acc.w += w.w*x;
    }
    sred[tid] = acc;
    __syncthreads();
    if (ds == 0){
        #pragma unroll
        for (int j=1;j<4;j++){
            const float4 o = sred[tid + j*64];
            acc.x += o.x; acc.y += o.y; acc.z += o.z; acc.w += o.w;
        }
        const int a = a0 + tx*4;
        acc.x += bd[a]   + be[a];
        acc.y += bd[a+1] + be[a+1];
        acc.z += bd[a+2] + be[a+2];
        acc.w += bd[a+3] + be[a+3];
        *(float4*)&g_c2[(size_t)(b0+bl)*A_ + a] = acc;
    }
}

// ============================================================
// K2: fused score GEMM (fp16 m16n8k16), cp.async 4-stage,
//     permuted layouts -> LDS.128 (B) / LDS.64 (A)
//   CTA 128x64, warps 4m x 2n, warp tile 32x32
//   grid (8 a-chunks, 196 m-tiles), 256 threads, 3 CTAs/SM
// ============================================================
#define MT 128
#define NT 64
#define KC 32
#define ASTRB 96              // A row stride bytes (64 data + 32 pad)
#define BSTRB 64              // B row stride bytes (16 words, no pad)
#define ABYTES (MT*ASTRB)     // 12288
#define BBYTES (NT*BSTRB)     // 4096
#define STGB (ABYTES+BBYTES)  // 16384
#define SMEM_K2 (4*STGB)      // 65536
#define NCH (E_/KC)           // 64

__global__ __launch_bounds__(256,3) void score_kernel(const float* __restrict__ Wf)
{
    extern __shared__ __align__(16) char smem[];
    const uint32_t sbase = smem_u32(smem);

    const int tid  = threadIdx.x;
    const int lane = tid & 31, warp = tid >> 5;
    const int wm = (warp >> 1) * 32;   // warp m offset (0,32,64,96)
    const int wn = (warp & 1) * 32;    // warp n offset (0 or 32)
    const int m0 = blockIdx.y * MT;
    const int a0 = blockIdx.x * NT;

    // cp.async maps
    const int ar = tid >> 1, hh = tid & 1;     // A: 2 thr/row, 32B each
    const int br = tid >> 2, bq4 = tid & 3;    // B: 4 thr/row, 16B each
    const __half*   gAh = g_encP + (size_t)(m0 + ar)*E_ + hh*16;
    const uint32_t* gBp = g_Wp   + (size_t)(a0 + br)*(E_/2) + bq4*4;
    const uint32_t dA = sbase + ar*ASTRB + hh*32;
    const uint32_t dB = sbase + ABYTES + br*BSTRB + bq4*16;

    auto issue = [&](int cc){
        const uint32_t so = (cc & 3)*STGB;
        const __half* pa = gAh + cc*KC;
        cpasync16(so + dA,      pa);
        cpasync16(so + dA + 16, pa + 8);
        cpasync16(so + dB, gBp + cc*(KC/2));
        CP_COMMIT();
    };

    float acc[2][4][4];
    #pragma unroll
    for (int i=0;i<2;i++)
        #pragma unroll
        for (int j=0;j<4;j++)
            #pragma unroll
            for (int k=0;k<4;k++) acc[i][j][k] = 0.f;

    issue(0); issue(1); issue(2);

    const int q = lane >> 2;      // 0..7
    const int c = lane & 3;       // 0..3

    for (int kc=0; kc<NCH; kc++){
        if (kc <= NCH-3)      { CP_WAIT2(); }
        else if (kc == NCH-2) { CP_WAIT1(); }
        else                  { CP_WAIT0(); }
        __syncthreads();
        // stage (kc+3)%4 == stage (kc-1)%4; all warps are past reading it
        if (kc < NCH-3) issue(kc+3);

        const char* stg = smem + (kc & 3)*STGB;
        const char* cA  = stg;
        const char* cB  = stg + ABYTES;

        // B: one LDS.128 per ns covers both kk
        uint4 bq[4];
        #pragma unroll
        for (int ns=0; ns<4; ns++)
            bq[ns] = *(const uint4*)(cB + (wn + ns*8 + q)*BSTRB + 16*c);

        #pragma unroll
        for (int kk=0; kk<2; kk++){
            uint32_t af[2][4];
            #pragma unroll
            for (int ms=0; ms<2; ms++){
                const char* pr = cA + (wm + ms*16 + q)*ASTRB + kk*32 + 8*c;
                const uint2 lo = *(const uint2*)(pr);
                const uint2 hi = *(const uint2*)(pr + 8*ASTRB);
                af[ms][0] = lo.x; af[ms][1] = hi.x;
                af[ms][2] = lo.y; af[ms][3] = hi.y;
            }
            #pragma unroll
            for (int ms=0; ms<2; ms++)
                #pragma unroll
                for (int ns=0; ns<4; ns++){
                    const uint32_t b0r = kk ? bq[ns].z : bq[ns].x;
                    const uint32_t b1r = kk ? bq[ns].w : bq[ns].y;
                    mma16(acc[ms][ns][0],acc[ms][ns][1],acc[ms][ns][2],acc[ms][ns][3],
                          af[ms][0],af[ms][1],af[ms][2],af[ms][3], b0r, b1r);
                }
        }
    }

    // ---- epilogue: tanh(+c2) dot Wf, quad-reduce, write partials ----
    const int c2i = c*2;
    #pragma unroll
    for (int ms=0; ms<2; ms++){
        const int r0 = m0 + wm + ms*16 + q;
        const int r1 = r0 + 8;
        const int b0 = r0 / N_;
        const int b1 = r1 / N_;
        float s0 = 0.f, s1 = 0.f;
        #pragma unroll
        for (int ns=0; ns<4; ns++){
            const int ag = a0 + wn + ns*8 + c2i;
            const float w0 = __ldg(&Wf[ag]), w1 = __ldg(&Wf[ag+1]);
            const float c00 = g_c2[(size_t)b0*A_ + ag], c01 = g_c2[(size_t)b0*A_ + ag + 1];
            const float c10 = g_c2[(size_t)b1*A_ + ag], c11 = g_c2[(size_t)b1*A_ + ag + 1];
            s0 += tanhf(acc[ms][ns][0] + c00) * w0 + tanhf(acc[ms][ns][1] + c01) * w1;
            s1 += tanhf(acc[ms][ns][2] + c10) * w0 + tanhf(acc[ms][ns][3] + c11) * w1;
        }
        s0 += __shfl_xor_sync(0xffffffffu, s0, 1);
        s0 += __shfl_xor_sync(0xffffffffu, s0, 2);
        s1 += __shfl_xor_sync(0xffffffffu, s1, 1);
        s1 += __shfl_xor_sync(0xffffffffu, s1, 2);
        if (c == 0){
            g_sp[(size_t)r0*16 + blockIdx.x*2 + (warp & 1)] = s0;
            g_sp[(size_t)r1*16 + blockIdx.x*2 + (warp & 1)] = s1;
        }
    }
}

// ============================================================
// K3: softmax over n per batch (16 partial slices)
// ============================================================
__global__ __launch_bounds__(256) void softmax_kernel(float* __restrict__ alpha)
{
    __shared__ float sh[256];
    const int b = blockIdx.x, t = threadIdx.x;
    float val = 0.f;
    if (t < N_){
        const float* p = &g_sp[(size_t)(b*N_ + t)*16];
        #pragma unroll
        for (int j=0;j<16;j++) val += p[j];
    }
    sh[t] = (t < N_) ? val : -1e30f;
    __syncthreads();
    for (int s=128; s>0; s>>=1){
        if (t < s) sh[t] = fmaxf(sh[t], sh[t+s]);
        __syncthreads();
    }
    const float mx = sh[0];
    __syncthreads();
    const float e = (t < N_) ? expf(val - mx) : 0.f;
    sh[t] = e;
    __syncthreads();
    for (int s=128; s>0; s>>=1){
        if (t < s) sh[t] += sh[t+s];
        __syncthreads();
    }
    const float inv = 1.f / sh[0];
    if (t < N_) alpha[(size_t)b*N_ + t] = e * inv;
}

// ============================================================
// K4: context from permuted fp16 enc; writes de-permuted
// ============================================================
__global__ __launch_bounds__(512) void ctx_kernel(
    const float* __restrict__ alpha, float* __restrict__ out)
{
    __shared__ float sal[N_];
    __shared__ float4 sred[3][128];
    const int b = blockIdx.y;
    const int t = threadIdx.x;
    for (int i=t; i<N_; i+=512) sal[i] = alpha[(size_t)b*N_ + i];
    __syncthreads();

    const int col = t & 127;       // uint2 (4 permuted halves) within 512 chunk
    const int nq  = t >> 7;        // n-quarter 0..3
    const uint2* pe = (const uint2*)(g_encP + (size_t)b*N_*E_ + blockIdx.x*512) + col;
    const int n0 = nq * 49, n1 = n0 + 49;
    float4 acc = {0,0,0,0};
    #pragma unroll 7
    for (int n=n0; n<n1; n++){
        const float a = sal[n];
        const uint2 v = pe[(size_t)n*(E_/4)];
        const float2 f0 = __half22float2(*(const __half2*)&v.x);
        const float2 f1 = __half22float2(*(const __half2*)&v.y);
        acc.x += f0.x*a; acc.y += f0.y*a; acc.z += f1.x*a; acc.w += f1.y*a;
    }
    if (nq > 0) sred[nq-1][col] = acc;
    __syncthreads();
    if (nq == 0){
        #pragma unroll
        for (int j=0;j<3;j++){
            const float4 o = sred[j][col];
            acc.x += o.x; acc.y += o.y; acc.z += o.z; acc.w += o.w;
        }
        const int g = col >> 2, idx = col & 3;
        const int e0 = blockIdx.x*512 + g*16 + 2*idx;
        float* ob = out + (size_t)b*E_;
        *(float2*)(ob + e0)     = make_float2(acc.x, acc.y);
        *(float2*)(ob + e0 + 8) = make_float2(acc.z, acc.w);
    }
}

// ============================================================
extern "C" void kernel_launch(void* const* d_in, const int* in_sizes, int n_in,
                              void* d_out, int out_size)
{
    (void)in_sizes; (void)n_in; (void)out_size;
    const float* enc = (const float*)d_in[0];   // (B,N,E)
    const float* dec = (const float*)d_in[1];   // (B,D)
    const float* We  = (const float*)d_in[2];   // (E,A)
    const float* be  = (const float*)d_in[3];   // (A)
    const float* Wd  = (const float*)d_in[4];   // (D,A)
    const float* bd  = (const float*)d_in[5];   // (A)
    const float* Wf  = (const float*)d_in[6];   // (A,1)
    // d_in[7] = bf : softmax-invariant, unused

    float* ctx_out   = (float*)d_out;               // (B,E)
    float* alpha_out = ctx_out + (size_t)B_*E_;     // (B,N,1)

    cudaFuncSetAttribute(score_kernel, cudaFuncAttributeMaxDynamicSharedMemorySize, SMEM_K2);

    conv_enc<<<(int)(((size_t)M_*E_)/(256*16)), 256>>>(enc);  // idx 0
    pack_we<<<dim3(32,16), dim3(32,8)>>>(We);                 // idx 1
    att2_kernel<<<dim3(16,16), 256>>>(dec, Wd, bd, be);       // idx 2
    score_kernel<<<dim3(8,196), 256, SMEM_K2>>>(Wf);          // idx 3 -> profiled
    softmax_kernel<<<128, 256>>>(alpha_out);                  // idx 4
    ctx_kernel<<<dim3(4,128), 512>>>(alpha_out, ctx_out);     // idx 5
}